// round 3
// baseline (speedup 1.0000x reference)
#include <cuda_runtime.h>
#include <cstdint>

// Problem constants (fixed by setup_inputs)
#define B      2
#define NPTS   8192
#define D      256
#define NBINS  32
#define BIN    256
#define TOPK   16
#define NPROJ  16          // n_bins / 2
#define NCHUNK (B * NBINS) // 64 total chunks across batches

#define GEMM_BLOCKS  (NCHUNK * 4)          // 256
#define ROLE_MOD     6                      // 1 gemm block per 6
#define MEGA_GRID    (GEMM_BLOCKS * ROLE_MOD) // 1536
#define ZERO_BLOCKS  (MEGA_GRID - GEMM_BLOCKS)

// ---------------- scratch (device globals; no allocation allowed) ------------
__device__ int   g_bin_idx[B * NPTS];
__device__ int   g_order  [B * NPTS];
__device__ float g_dm     [NCHUNK * BIN * BIN]; // 16 MB sigmoid(similarity)

// ---------------- K1: projection + argmax over [proj, -proj] ------------------
__global__ __launch_bounds__(256) void k_proj_argmax(
    const float* __restrict__ x, const float* __restrict__ cb) {
    __shared__ float cbs[NPROJ][D];
    int tid = threadIdx.x;
    for (int e = tid; e < D * 32; e += 256) {
        int d = e >> 5, j = e & 31;
        float v = cb[e];
        if (j < NPROJ) cbs[j][d] = v;
    }
    __syncthreads();

    int warp = tid >> 5, lane = tid & 31;
    for (int i = 0; i < 8; i++) {
        int p = blockIdx.x * 64 + warp * 8 + i;
        const float* xr = x + (size_t)p * D;
        float acc[NPROJ];
#pragma unroll
        for (int j = 0; j < NPROJ; j++) acc[j] = 0.f;
#pragma unroll
        for (int k = 0; k < 8; k++) {
            int d = lane + 32 * k;
            float xv = xr[d];
#pragma unroll
            for (int j = 0; j < NPROJ; j++) acc[j] += xv * cbs[j][d];
        }
#pragma unroll
        for (int j = 0; j < NPROJ; j++)
#pragma unroll
            for (int off = 16; off; off >>= 1)
                acc[j] += __shfl_xor_sync(0xFFFFFFFFu, acc[j], off);
        if (lane == 0) {
            float best = acc[0]; int bi = 0;
            for (int jj = 1; jj < 2 * NPROJ; jj++) {
                float v = (jj < NPROJ) ? acc[jj] : -acc[jj - NPROJ];
                if (v > best) { best = v; bi = jj; }
            }
            g_bin_idx[p] = bi;
        }
    }
}

// ---------------- K2: stable counting sort (argsort by bin id) ---------------
__global__ __launch_bounds__(1024) void k_stable_sort() {
    int batch = blockIdx.x;
    const int* bi = g_bin_idx + batch * NPTS;
    int* ord = g_order + batch * NPTS;
    __shared__ int off[NBINS + 1];
    int w = threadIdx.x >> 5, lane = threadIdx.x & 31;

    int total = 0;
    for (int it = 0; it < NPTS / 32; it++) {
        int i = it * 32 + lane;
        unsigned m = __ballot_sync(0xFFFFFFFFu, bi[i] == w);
        total += __popc(m);
    }
    if (lane == 0) off[w + 1] = total;
    __syncthreads();
    if (threadIdx.x == 0) {
        off[0] = 0;
        for (int j = 1; j <= NBINS; j++) off[j] += off[j - 1];
    }
    __syncthreads();

    int pos = off[w];
    for (int it = 0; it < NPTS / 32; it++) {
        int i = it * 32 + lane;
        int b = bi[i];
        unsigned m = __ballot_sync(0xFFFFFFFFu, b == w);
        if (b == w) ord[pos + __popc(m & ((1u << lane) - 1u))] = i;
        pos += __popc(m);
    }
}

// ---------------- K3 mega: role-split {GEMM+sigmoid | zero-fill} -------------
// blockIdx % 6 == 0  -> gemm block (id = blockIdx/6, 256 of them)
// otherwise          -> grid-stride zero-fill of the 512MB output
__global__ __launch_bounds__(256, 2) void k_mega(const float* __restrict__ x,
                                                 float4* __restrict__ out4) {
    int bx = blockIdx.x;
    if ((bx % ROLE_MOD) != 0) {
        // ---- zero role ----
        int zid = bx - bx / ROLE_MOD - 1; // dense id in [0, ZERO_BLOCKS)
        const long n4 = (long)B * NPTS * NPTS / 4;
        const long stride = (long)ZERO_BLOCKS * 256;
        float4 z = make_float4(0.f, 0.f, 0.f, 0.f);
        for (long i = (long)zid * 256 + threadIdx.x; i < n4; i += stride)
            out4[i] = z;
        return;
    }

    // ---- gemm role ----
    int gid = bx / ROLE_MOD; // 0..255
    __shared__ float As[8][132];
    __shared__ float Bs[8][132];

    int chunk = gid >> 2;
    int b     = chunk >> 5;
    int cbase = (chunk & 31) * BIN;
    int row0  = ((gid >> 1) & 1) * 128;
    int col0  = (gid & 1) * 128;

    int tid = threadIdx.x;
    int halfrow = tid >> 1;
    int q = tid & 1;

    int srcA = g_order[b * NPTS + cbase + row0 + halfrow];
    int srcB = g_order[b * NPTS + cbase + col0 + halfrow];
    const float4* pA = (const float4*)(x + ((size_t)b * NPTS + srcA) * D) + q;
    const float4* pB = (const float4*)(x + ((size_t)b * NPTS + srcB) * D) + q;

    int tx = tid & 15, ty = tid >> 4;

    float acc[8][8];
#pragma unroll
    for (int i = 0; i < 8; i++)
#pragma unroll
        for (int j = 0; j < 8; j++) acc[i][j] = 0.f;

    for (int kt = 0; kt < D; kt += 8) {
        float4 va = pA[kt >> 2];
        float4 vb = pB[kt >> 2];
        __syncthreads();
        As[4 * q + 0][halfrow] = va.x;
        As[4 * q + 1][halfrow] = va.y;
        As[4 * q + 2][halfrow] = va.z;
        As[4 * q + 3][halfrow] = va.w;
        Bs[4 * q + 0][halfrow] = vb.x;
        Bs[4 * q + 1][halfrow] = vb.y;
        Bs[4 * q + 2][halfrow] = vb.z;
        Bs[4 * q + 3][halfrow] = vb.w;
        __syncthreads();
#pragma unroll
        for (int kk = 0; kk < 8; kk++) {
            float a[8], bb[8];
#pragma unroll
            for (int i = 0; i < 8; i++) a[i] = As[kk][ty * 8 + i];
#pragma unroll
            for (int j = 0; j < 8; j++) bb[j] = Bs[kk][tx * 8 + j];
#pragma unroll
            for (int i = 0; i < 8; i++)
#pragma unroll
                for (int j = 0; j < 8; j++) acc[i][j] += a[i] * bb[j];
        }
    }

    float* C = g_dm + (size_t)chunk * BIN * BIN;
#pragma unroll
    for (int i = 0; i < 8; i++) {
        int rr = row0 + ty * 8 + i;
#pragma unroll
        for (int jj = 0; jj < 2; jj++) {
            float4 o;
            o.x = 1.f / (1.f + expf(-acc[i][4 * jj + 0]));
            o.y = 1.f / (1.f + expf(-acc[i][4 * jj + 1]));
            o.z = 1.f / (1.f + expf(-acc[i][4 * jj + 2]));
            o.w = 1.f / (1.f + expf(-acc[i][4 * jj + 3]));
            *(float4*)(C + (size_t)rr * BIN + col0 + tx * 8 + 4 * jj) = o;
        }
    }
}

// ---------------- K4: top-16 per row + scatter (output already zeroed) -------
// one warp per row; 16384 rows; 2048 blocks x 256 threads
__global__ __launch_bounds__(256) void k_topk_scatter(float* __restrict__ out) {
    int warp = threadIdx.x >> 5, lane = threadIdx.x & 31;
    int row_g = blockIdx.x * 8 + warp;   // [0, B*NPTS)
    const float* r = g_dm + (size_t)row_g * BIN;

    unsigned u[8];
#pragma unroll
    for (int q = 0; q < 8; q++) u[q] = __float_as_uint(r[lane + 32 * q]);

    int b = row_g >> 13;
    int jrow = row_g & (NPTS - 1);
    int chunkoff = b * NPTS + (jrow & ~(BIN - 1));
    int gsrc = g_order[row_g];
    float* orow = out + ((size_t)b * NPTS + gsrc) * NPTS;

    for (int it = 0; it < TOPK; it++) {
        unsigned best = 0u; int bc = BIN;
#pragma unroll
        for (int q = 0; q < 8; q++) {
            // ascending c within lane + strict '>' keeps min col on ties
            if (u[q] > best) { best = u[q]; bc = lane + 32 * q; }
        }
        unsigned m = __reduce_max_sync(0xFFFFFFFFu, best);
        int cand = (best == m) ? bc : (1 << 30);
        int cmin = __reduce_min_sync(0xFFFFFFFFu, cand);
        if ((cmin & 31) == lane) u[cmin >> 5] = 0u; // sigmoid > 0: 0 == consumed
        if (lane == it) { // spread the 16 scattered stores across lanes
            int gdst = g_order[chunkoff + cmin];
            orow[gdst] = __uint_as_float(m); // (gsrc,gdst) unique -> plain store
        }
    }
}

// ---------------- launch ------------------------------------------------------
extern "C" void kernel_launch(void* const* d_in, const int* in_sizes, int n_in,
                              void* d_out, int out_size) {
    const float* x  = (const float*)d_in[0]; // (2, 8192, 256) f32
    const float* cb = (const float*)d_in[1]; // (256, 32) f32
    float* out = (float*)d_out;              // (2, 8192, 8192) f32

    k_proj_argmax<<<(B * NPTS) / 64, 256>>>(x, cb);
    k_stable_sort<<<B, 1024>>>();
    k_mega<<<MEGA_GRID, 256>>>(x, (float4*)out);
    k_topk_scatter<<<(B * NPTS) / 8, 256>>>(out);
}

// round 4
// speedup vs baseline: 1.1258x; 1.1258x over previous
#include <cuda_runtime.h>
#include <cstdint>

// Problem constants (fixed by setup_inputs)
#define B      2
#define NPTS   8192
#define D      256
#define NBINS  32
#define BIN    256
#define TOPK   16
#define NPROJ  16          // n_bins / 2
#define NCHUNK (B * NBINS) // 64 total chunks across batches
#define KP     16          // k-panel depth for GEMM

// ---------------- scratch (device globals; no allocation allowed) ------------
__device__ int   g_bin_idx[B * NPTS];
__device__ int   g_order  [B * NPTS];
__device__ float g_dm     [NCHUNK * BIN * BIN]; // 16 MB sigmoid(similarity)
__device__ int   g_dst    [B * NPTS * TOPK];    // top-k destination indices
__device__ float g_val    [B * NPTS * TOPK];    // top-k values

// upper-triangle 64x64 tile list for a 256x256 chunk (4x4 tile grid)
__constant__ int c_TI[10] = {0,0,0,0,1,1,1,2,2,3};
__constant__ int c_TJ[10] = {0,1,2,3,1,2,3,2,3,3};

// ---------------- K1: projection + argmax over [proj, -proj] ------------------
__global__ __launch_bounds__(256) void k_proj_argmax(
    const float* __restrict__ x, const float* __restrict__ cb) {
    __shared__ float cbs[NPROJ][D];
    int tid = threadIdx.x;
    for (int e = tid; e < D * 32; e += 256) {
        int d = e >> 5, j = e & 31;
        float v = cb[e];
        if (j < NPROJ) cbs[j][d] = v;
    }
    __syncthreads();

    int warp = tid >> 5, lane = tid & 31;
    for (int i = 0; i < 8; i++) {
        int p = blockIdx.x * 64 + warp * 8 + i;
        const float* xr = x + (size_t)p * D;
        float acc[NPROJ];
#pragma unroll
        for (int j = 0; j < NPROJ; j++) acc[j] = 0.f;
#pragma unroll
        for (int k = 0; k < 8; k++) {
            int d = lane + 32 * k;
            float xv = xr[d];
#pragma unroll
            for (int j = 0; j < NPROJ; j++) acc[j] += xv * cbs[j][d];
        }
#pragma unroll
        for (int j = 0; j < NPROJ; j++)
#pragma unroll
            for (int off = 16; off; off >>= 1)
                acc[j] += __shfl_xor_sync(0xFFFFFFFFu, acc[j], off);
        if (lane == 0) {
            float best = acc[0]; int bi = 0;
            for (int jj = 1; jj < 2 * NPROJ; jj++) {
                float v = (jj < NPROJ) ? acc[jj] : -acc[jj - NPROJ];
                if (v > best) { best = v; bi = jj; }
            }
            g_bin_idx[p] = bi;
        }
    }
}

// ---------------- K2: stable counting sort (argsort by bin id) ---------------
__global__ __launch_bounds__(1024) void k_stable_sort() {
    int batch = blockIdx.x;
    const int* bi = g_bin_idx + batch * NPTS;
    int* ord = g_order + batch * NPTS;
    __shared__ int off[NBINS + 1];
    int w = threadIdx.x >> 5, lane = threadIdx.x & 31;

    int total = 0;
    for (int it = 0; it < NPTS / 32; it++) {
        int i = it * 32 + lane;
        unsigned m = __ballot_sync(0xFFFFFFFFu, bi[i] == w);
        total += __popc(m);
    }
    if (lane == 0) off[w + 1] = total;
    __syncthreads();
    if (threadIdx.x == 0) {
        off[0] = 0;
        for (int j = 1; j <= NBINS; j++) off[j] += off[j - 1];
    }
    __syncthreads();

    int pos = off[w];
    for (int it = 0; it < NPTS / 32; it++) {
        int i = it * 32 + lane;
        int b = bi[i];
        unsigned m = __ballot_sync(0xFFFFFFFFu, b == w);
        if (b == w) ord[pos + __popc(m & ((1u << lane) - 1u))] = i;
        pos += __popc(m);
    }
}

// ---------------- K3: symmetric fused gather+GEMM+sigmoid --------------------
// 64x64 tiles over the upper triangle of each 256x256 chunk (10 tiles/chunk).
// 64 threads/block, 8x8 per-thread accumulators. Off-diagonal tiles also write
// the mirrored (transposed) tile with float4 stores built from registers.
__global__ __launch_bounds__(64) void k_gemm_sym(const float* __restrict__ x) {
    __shared__ float As[KP][68];
    __shared__ float Bs[KP][68];

    int t     = blockIdx.x % 10;
    int chunk = blockIdx.x / 10;
    int b     = chunk >> 5;
    int cbase = (chunk & 31) * BIN;
    int ti = c_TI[t], tj = c_TJ[t];
    int row0 = ti * 64, col0 = tj * 64;

    int tid = threadIdx.x;
    int q = tid & 3;       // which float4 of the 16-wide k panel
    int rbase = tid >> 2;  // 0..15

    const float* aptr[4];
    const float* bptr[4];
#pragma unroll
    for (int l = 0; l < 4; l++) {
        int r = rbase + 16 * l;
        int sA = g_order[b * NPTS + cbase + row0 + r];
        int sB = g_order[b * NPTS + cbase + col0 + r];
        aptr[l] = x + ((size_t)b * NPTS + sA) * D + q * 4;
        bptr[l] = x + ((size_t)b * NPTS + sB) * D + q * 4;
    }

    int tx = tid & 7, ty = tid >> 3;

    float acc[8][8];
#pragma unroll
    for (int i = 0; i < 8; i++)
#pragma unroll
        for (int j = 0; j < 8; j++) acc[i][j] = 0.f;

    float4 va[4], vb[4];
#pragma unroll
    for (int l = 0; l < 4; l++) {
        va[l] = *(const float4*)(aptr[l]);
        vb[l] = *(const float4*)(bptr[l]);
    }

    for (int kt = 0; kt < D; kt += KP) {
        __syncthreads(); // previous compute done reading smem
#pragma unroll
        for (int l = 0; l < 4; l++) {
            int r = rbase + 16 * l;
            As[q * 4 + 0][r] = va[l].x;
            As[q * 4 + 1][r] = va[l].y;
            As[q * 4 + 2][r] = va[l].z;
            As[q * 4 + 3][r] = va[l].w;
            Bs[q * 4 + 0][r] = vb[l].x;
            Bs[q * 4 + 1][r] = vb[l].y;
            Bs[q * 4 + 2][r] = vb[l].z;
            Bs[q * 4 + 3][r] = vb[l].w;
        }
        __syncthreads();
        if (kt + KP < D) { // prefetch next panel while computing
#pragma unroll
            for (int l = 0; l < 4; l++) {
                va[l] = *(const float4*)(aptr[l] + kt + KP);
                vb[l] = *(const float4*)(bptr[l] + kt + KP);
            }
        }
#pragma unroll
        for (int kk = 0; kk < KP; kk++) {
            float4 a0 = *(const float4*)&As[kk][ty * 8];
            float4 a1 = *(const float4*)&As[kk][ty * 8 + 4];
            float4 b0 = *(const float4*)&Bs[kk][tx * 8];
            float4 b1 = *(const float4*)&Bs[kk][tx * 8 + 4];
            float a[8] = {a0.x, a0.y, a0.z, a0.w, a1.x, a1.y, a1.z, a1.w};
            float bb[8] = {b0.x, b0.y, b0.z, b0.w, b1.x, b1.y, b1.z, b1.w};
#pragma unroll
            for (int i = 0; i < 8; i++)
#pragma unroll
                for (int j = 0; j < 8; j++) acc[i][j] += a[i] * bb[j];
        }
    }

    // sigmoid in place
#pragma unroll
    for (int i = 0; i < 8; i++)
#pragma unroll
        for (int j = 0; j < 8; j++)
            acc[i][j] = 1.f / (1.f + expf(-acc[i][j]));

    float* C = g_dm + (size_t)chunk * BIN * BIN;
    // normal tile write
#pragma unroll
    for (int i = 0; i < 8; i++) {
        int rr = row0 + ty * 8 + i;
        *(float4*)(C + (size_t)rr * BIN + col0 + tx * 8) =
            make_float4(acc[i][0], acc[i][1], acc[i][2], acc[i][3]);
        *(float4*)(C + (size_t)rr * BIN + col0 + tx * 8 + 4) =
            make_float4(acc[i][4], acc[i][5], acc[i][6], acc[i][7]);
    }
    // mirror tile write (transposed), off-diagonal only
    if (ti != tj) {
#pragma unroll
        for (int j = 0; j < 8; j++) {
            int rr = col0 + tx * 8 + j;
            *(float4*)(C + (size_t)rr * BIN + row0 + ty * 8) =
                make_float4(acc[0][j], acc[1][j], acc[2][j], acc[3][j]);
            *(float4*)(C + (size_t)rr * BIN + row0 + ty * 8 + 4) =
                make_float4(acc[4][j], acc[5][j], acc[6][j], acc[7][j]);
        }
    }
}

// ---------------- K4: zero output rows + top-16 (no barrier coupling) --------
// one block per output row; warp 0 computes top-16 into g_dst/g_val,
// warps 1-7 stream-zero the 32KB row. No __syncthreads.
__global__ __launch_bounds__(256) void k_zero_topk(float* __restrict__ out) {
    int row_g = blockIdx.x;              // [0, B*NPTS)
    int lane = threadIdx.x & 31, w = threadIdx.x >> 5;
    int b = row_g >> 13;
    int jrow = row_g & (NPTS - 1);

    if (w == 0) {
        const float* r = g_dm + (size_t)row_g * BIN;
        unsigned u[8];
#pragma unroll
        for (int q = 0; q < 8; q++) u[q] = __float_as_uint(r[lane + 32 * q]);
        int chunkoff = b * NPTS + (jrow & ~(BIN - 1));
        for (int it = 0; it < TOPK; it++) {
            unsigned best = 0u; int bc = BIN;
#pragma unroll
            for (int q = 0; q < 8; q++) {
                // ascending c within lane + strict '>' keeps min col on ties
                if (u[q] > best) { best = u[q]; bc = lane + 32 * q; }
            }
            unsigned m = __reduce_max_sync(0xFFFFFFFFu, best);
            int cand = (best == m) ? bc : (1 << 30);
            int cmin = __reduce_min_sync(0xFFFFFFFFu, cand);
            if ((cmin & 31) == lane) u[cmin >> 5] = 0u; // sigmoid > 0
            if (lane == it) {
                g_val[row_g * TOPK + it] = __uint_as_float(m);
                g_dst[row_g * TOPK + it] = g_order[chunkoff + cmin];
            }
        }
    } else {
        int gsrc = g_order[row_g];
        float4* o4 = (float4*)(out + ((size_t)b * NPTS + gsrc) * NPTS);
        float4 z = make_float4(0.f, 0.f, 0.f, 0.f);
        for (int i = threadIdx.x - 32; i < NPTS / 4; i += 224) o4[i] = z;
    }
}

// ---------------- K5: apply the 262144 top-k stores (after zeroing) ----------
__global__ __launch_bounds__(256) void k_scatter(float* __restrict__ out) {
    int i = blockIdx.x * 256 + threadIdx.x; // [0, B*NPTS*TOPK)
    int row_g = i >> 4;
    int b = row_g >> 13;
    int gsrc = g_order[row_g];
    out[((size_t)b * NPTS + gsrc) * NPTS + g_dst[i]] = g_val[i];
}

// ---------------- launch ------------------------------------------------------
extern "C" void kernel_launch(void* const* d_in, const int* in_sizes, int n_in,
                              void* d_out, int out_size) {
    const float* x  = (const float*)d_in[0]; // (2, 8192, 256) f32
    const float* cb = (const float*)d_in[1]; // (256, 32) f32
    float* out = (float*)d_out;              // (2, 8192, 8192) f32

    k_proj_argmax<<<(B * NPTS) / 64, 256>>>(x, cb);
    k_stable_sort<<<B, 1024>>>();
    k_gemm_sym<<<NCHUNK * 10, 64>>>(x);
    k_zero_topk<<<B * NPTS, 256>>>(out);
    k_scatter<<<(B * NPTS * TOPK) / 256, 256>>>(out);
}